// round 4
// baseline (speedup 1.0000x reference)
#include <cuda_runtime.h>
#include <cuda_bf16.h>

// k-winners-take-all over channels: x (rows=200704, C=256) fp32.
// Keep x >= (26th largest in row), else 0.
// Warp-per-row, exact MSB radix select with data-driven early exit.

constexpr int CHANNELS = 256;
constexpr unsigned KSEL = 26;   // max(1, round(0.1 * 256))

// Order-preserving float->uint key (ascending). 2 inst: SHF.R.S32 + LOP3.
__device__ __forceinline__ unsigned f2k(float f) {
    unsigned u = __float_as_uint(f);
    unsigned m = (unsigned)((int)u >> 31);
    return u ^ (m | 0x80000000u);        // single LOP3: a ^ (b | c)
}

// compare-exchange: a <- max, b <- min  (descending sort)
__device__ __forceinline__ void ce(unsigned &a, unsigned &b) {
    unsigned hi = a > b ? a : b;
    unsigned lo = a > b ? b : a;
    a = hi; b = lo;
}

__global__ void __launch_bounds__(256)
kwta_kernel(const float* __restrict__ x, float* __restrict__ y, int rows) {
    int gw = (blockIdx.x * blockDim.x + threadIdx.x) >> 5;   // global warp = row
    if (gw >= rows) return;
    int lane = threadIdx.x & 31;

    const float4* xp = reinterpret_cast<const float4*>(x) + (size_t)gw * (CHANNELS / 4);
    float4 a = __ldcs(xp + lane);
    float4 b = __ldcs(xp + 32 + lane);

    unsigned s0 = f2k(a.x), s1 = f2k(a.y), s2 = f2k(a.z), s3 = f2k(a.w);
    unsigned s4 = f2k(b.x), s5 = f2k(b.y), s6 = f2k(b.z), s7 = f2k(b.w);

    // Batcher odd-even mergesort for 8, descending (19 CE)
    ce(s0,s1); ce(s2,s3); ce(s4,s5); ce(s6,s7);
    ce(s0,s2); ce(s1,s3); ce(s4,s6); ce(s5,s7);
    ce(s1,s2); ce(s5,s6);
    ce(s0,s4); ce(s1,s5); ce(s2,s6); ce(s3,s7);
    ce(s2,s4); ce(s3,s5);
    ce(s1,s2); ce(s3,s4); ce(s5,s6);
    // s0 >= s1 >= ... >= s7

    // MSB radix select for the KSEL-th largest key, with early exit when the
    // bracket [prefix, U) isolates a single element.
    unsigned prefix = 0u;            // cnt_ge(prefix) >= KSEL always
    unsigned U      = 0xFFFFFFFFu;   // cnt_ge(U) < KSEL (0xFFFFFFFF = NaN key, absent)
    unsigned cntP   = 256u;          // cnt_ge(prefix)
    unsigned cntU   = 0u;            // cnt_ge(U)
    unsigned thrkey;

    #pragma unroll 1
    for (int bit = 31; ; --bit) {
        unsigned cand = prefix | (1u << bit);
        // per-lane cnt = #{s_i >= cand}, branchless binary search on sorted regs
        bool c1 = (s3 >= cand);
        unsigned t1 = c1 ? s5 : s1;
        bool c2 = (t1 >= cand);
        unsigned tA = c2 ? s2 : s0;
        unsigned tB = c2 ? s6 : s4;
        unsigned t2 = c1 ? tB : tA;
        bool c3 = (t2 >= cand);
        bool c0 = (s7 >= cand);
        unsigned cnt = 4u * (unsigned)c1 + 2u * (unsigned)c2
                     + (unsigned)c3 + (unsigned)c0;
        unsigned tot = __reduce_add_sync(0xFFFFFFFFu, cnt);
        if (tot >= KSEL) { prefix = cand; cntP = tot; }
        else             { U = cand;      cntU = tot; }

        if (cntP - cntU == 1u) {
            // exactly one key in [prefix, U): it is the KSEL-th largest.
            // per-lane: largest s_j with s_j < U (sorted desc -> first such)
            unsigned t = s7;
            t = (s6 < U) ? s6 : t;
            t = (s5 < U) ? s5 : t;
            t = (s4 < U) ? s4 : t;
            t = (s3 < U) ? s3 : t;
            t = (s2 < U) ? s2 : t;
            t = (s1 < U) ? s1 : t;
            t = (s0 < U) ? s0 : t;
            unsigned m = (t >= prefix && t < U) ? t : 0u;
            thrkey = __reduce_max_sync(0xFFFFFFFFu, m);
            break;
        }
        if (bit == 0) { thrkey = prefix; break; }
    }

    // unmap key -> float threshold
    unsigned tu = (thrkey & 0x80000000u) ? (thrkey ^ 0x80000000u) : ~thrkey;
    float thr = __uint_as_float(tu);

    float4 oa, ob;
    oa.x = (a.x >= thr) ? a.x : 0.0f;
    oa.y = (a.y >= thr) ? a.y : 0.0f;
    oa.z = (a.z >= thr) ? a.z : 0.0f;
    oa.w = (a.w >= thr) ? a.w : 0.0f;
    ob.x = (b.x >= thr) ? b.x : 0.0f;
    ob.y = (b.y >= thr) ? b.y : 0.0f;
    ob.z = (b.z >= thr) ? b.z : 0.0f;
    ob.w = (b.w >= thr) ? b.w : 0.0f;

    float4* yp = reinterpret_cast<float4*>(y) + (size_t)gw * (CHANNELS / 4);
    __stcs(yp + lane, oa);
    __stcs(yp + 32 + lane, ob);
}

extern "C" void kernel_launch(void* const* d_in, const int* in_sizes, int n_in,
                              void* d_out, int out_size) {
    const float* x = (const float*)d_in[0];
    float* y = (float*)d_out;
    int rows = in_sizes[0] / CHANNELS;            // 200704
    int total_threads = rows * 32;                // one warp per row
    int block = 256;
    int grid = (total_threads + block - 1) / block;
    kwta_kernel<<<grid, block>>>(x, y, rows);
}

// round 5
// speedup vs baseline: 1.3360x; 1.3360x over previous
#include <cuda_runtime.h>
#include <cuda_bf16.h>

// k-winners-take-all: x (rows=200704, C=256) fp32. Keep x >= 26th largest per row.
// Warp-per-row. Hot path: float-domain radix select on positive bit patterns
// (FSETP/FSEL -> fma pipe, free candidate reinterpret). Cold path (threshold<0,
// ~never for this data but required for exactness): key-domain radix.

constexpr int CHANNELS = 256;
constexpr unsigned KSEL = 26;   // max(1, round(0.1 * 256))

__device__ __forceinline__ void ceF(float &a, float &b) {   // a<-max, b<-min (FMNMX x2)
    float hi = fmaxf(a, b), lo = fminf(a, b);
    a = hi; b = lo;
}

__device__ __forceinline__ unsigned f2k(float f) {          // order-preserving key
    unsigned u = __float_as_uint(f);
    unsigned m = (unsigned)((int)u >> 31);
    return u ^ (m | 0x80000000u);
}

__global__ void __launch_bounds__(256)
kwta_kernel(const float* __restrict__ x, float* __restrict__ y, int rows) {
    int gw = (blockIdx.x * blockDim.x + threadIdx.x) >> 5;
    if (gw >= rows) return;
    int lane = threadIdx.x & 31;

    const float4* xp = reinterpret_cast<const float4*>(x) + (size_t)gw * (CHANNELS / 4);
    float4 a = __ldcs(xp + lane);
    float4 b = __ldcs(xp + 32 + lane);

    float f0 = a.x, f1 = a.y, f2 = a.z, f3 = a.w;
    float f4 = b.x, f5 = b.y, f6 = b.z, f7 = b.w;

    // Batcher odd-even mergesort for 8, descending (19 CE = 38 FMNMX, alu pipe)
    ceF(f0,f1); ceF(f2,f3); ceF(f4,f5); ceF(f6,f7);
    ceF(f0,f2); ceF(f1,f3); ceF(f4,f6); ceF(f5,f7);
    ceF(f1,f2); ceF(f5,f6);
    ceF(f0,f4); ceF(f1,f5); ceF(f2,f6); ceF(f3,f7);
    ceF(f2,f4); ceF(f3,f5);
    ceF(f1,f2); ceF(f3,f4); ceF(f5,f6);
    // f0 >= f1 >= ... >= f7

    // per-lane count of {f_j >= c} via branchless binary search (FSETP/FSEL)
    auto cnt8 = [&](float c) -> unsigned {
        bool c1 = (f3 >= c);
        float t1 = c1 ? f5 : f1;
        bool c2 = (t1 >= c);
        float tA = c2 ? f2 : f0;
        float tB = c2 ? f6 : f4;
        float t2 = c1 ? tB : tA;
        bool c3 = (t2 >= c);
        bool c0 = (f7 >= c);
        return 4u*(unsigned)c1 + 2u*(unsigned)c2 + (unsigned)c3 + (unsigned)c0;
    };

    unsigned cnt_pos = __reduce_add_sync(0xFFFFFFFFu, cnt8(0.0f));
    float thrf;

    if (cnt_pos >= KSEL) {
        // ---- HOT: threshold >= 0; positive patterns order like floats ----
        unsigned prefix = 0u;            // cnt_ge >= KSEL
        unsigned U      = 0x7F800000u;   // +Inf pattern: cnt_ge = 0
        unsigned cntP   = cnt_pos, cntU = 0u;
        unsigned thrkey;

        #pragma unroll 1
        for (int bit = 30; ; --bit) {
            unsigned cand = prefix | (1u << bit);
            unsigned tot = __reduce_add_sync(0xFFFFFFFFu, cnt8(__uint_as_float(cand)));
            if (tot >= KSEL) { prefix = cand; cntP = tot; }
            else             { U = cand;      cntU = tot; }

            if (cntP - cntU == 1u) {
                // unique element in [prefixf, Uf): it's the KSEL-th largest
                float Uf = __uint_as_float(U);
                float pf = __uint_as_float(prefix);
                float t = f7;
                t = (f6 < Uf) ? f6 : t;
                t = (f5 < Uf) ? f5 : t;
                t = (f4 < Uf) ? f4 : t;
                t = (f3 < Uf) ? f3 : t;
                t = (f2 < Uf) ? f2 : t;
                t = (f1 < Uf) ? f1 : t;
                t = (f0 < Uf) ? f0 : t;
                unsigned m = (t >= pf && t < Uf) ? __float_as_uint(t) : 0u;
                thrkey = __reduce_max_sync(0xFFFFFFFFu, m);
                break;
            }
            if (bit == 0) { thrkey = prefix; break; }
        }
        thrf = __uint_as_float(thrkey);
    } else {
        // ---- COLD: threshold < 0; exact key-domain radix (rarely taken) ----
        unsigned s0 = f2k(f0), s1 = f2k(f1), s2 = f2k(f2), s3 = f2k(f3);
        unsigned s4 = f2k(f4), s5 = f2k(f5), s6 = f2k(f6), s7 = f2k(f7);
        auto kcnt8 = [&](unsigned c) -> unsigned {
            bool c1 = (s3 >= c);
            unsigned t1 = c1 ? s5 : s1;
            bool c2 = (t1 >= c);
            unsigned tA = c2 ? s2 : s0;
            unsigned tB = c2 ? s6 : s4;
            unsigned t2 = c1 ? tB : tA;
            bool c3 = (t2 >= c);
            bool c0 = (s7 >= c);
            return 4u*(unsigned)c1 + 2u*(unsigned)c2 + (unsigned)c3 + (unsigned)c0;
        };
        unsigned prefix = 0u, U = 0xFFFFFFFFu;
        unsigned cntP = 256u, cntU = 0u;
        unsigned thrkey;
        #pragma unroll 1
        for (int bit = 31; ; --bit) {
            unsigned cand = prefix | (1u << bit);
            unsigned tot = __reduce_add_sync(0xFFFFFFFFu, kcnt8(cand));
            if (tot >= KSEL) { prefix = cand; cntP = tot; }
            else             { U = cand;      cntU = tot; }
            if (cntP - cntU == 1u) {
                unsigned t = s7;
                t = (s6 < U) ? s6 : t;
                t = (s5 < U) ? s5 : t;
                t = (s4 < U) ? s4 : t;
                t = (s3 < U) ? s3 : t;
                t = (s2 < U) ? s2 : t;
                t = (s1 < U) ? s1 : t;
                t = (s0 < U) ? s0 : t;
                unsigned m = (t >= prefix && t < U) ? t : 0u;
                thrkey = __reduce_max_sync(0xFFFFFFFFu, m);
                break;
            }
            if (bit == 0) { thrkey = prefix; break; }
        }
        unsigned tu = (thrkey & 0x80000000u) ? (thrkey ^ 0x80000000u) : ~thrkey;
        thrf = __uint_as_float(tu);
    }

    float4 oa, ob;
    oa.x = (a.x >= thrf) ? a.x : 0.0f;
    oa.y = (a.y >= thrf) ? a.y : 0.0f;
    oa.z = (a.z >= thrf) ? a.z : 0.0f;
    oa.w = (a.w >= thrf) ? a.w : 0.0f;
    ob.x = (b.x >= thrf) ? b.x : 0.0f;
    ob.y = (b.y >= thrf) ? b.y : 0.0f;
    ob.z = (b.z >= thrf) ? b.z : 0.0f;
    ob.w = (b.w >= thrf) ? b.w : 0.0f;

    float4* yp = reinterpret_cast<float4*>(y) + (size_t)gw * (CHANNELS / 4);
    __stcs(yp + lane, oa);
    __stcs(yp + 32 + lane, ob);
}

extern "C" void kernel_launch(void* const* d_in, const int* in_sizes, int n_in,
                              void* d_out, int out_size) {
    const float* x = (const float*)d_in[0];
    float* y = (float*)d_out;
    int rows = in_sizes[0] / CHANNELS;            // 200704
    int total_threads = rows * 32;                // one warp per row
    int block = 256;
    int grid = (total_threads + block - 1) / block;
    kwta_kernel<<<grid, block>>>(x, y, rows);
}

// round 6
// speedup vs baseline: 1.7337x; 1.2977x over previous
#include <cuda_runtime.h>
#include <cuda_bf16.h>

// k-winners-take-all: x (rows=200704, C=256) fp32. Keep x >= 26th largest per row.
// Warp-per-row. Hot path: integer bisection on positive-float bit patterns with
// data-derived bounds [min-lane-max, warp-max] and single-element early exit.
// Cold path (threshold < 0; ~never on this data, needed for exactness): key radix.

constexpr int CHANNELS = 256;
constexpr unsigned KSEL = 26;   // max(1, round(0.1 * 256))

__device__ __forceinline__ void ceF(float &a, float &b) {   // a<-max, b<-min
    float hi = fmaxf(a, b), lo = fminf(a, b);
    a = hi; b = lo;
}

__device__ __forceinline__ unsigned f2k(float f) {          // order-preserving key
    unsigned u = __float_as_uint(f);
    unsigned m = (unsigned)((int)u >> 31);
    return u ^ (m | 0x80000000u);
}

__global__ void __launch_bounds__(256)
kwta_kernel(const float* __restrict__ x, float* __restrict__ y, int rows) {
    int gw = (blockIdx.x * blockDim.x + threadIdx.x) >> 5;
    if (gw >= rows) return;
    int lane = threadIdx.x & 31;

    const float4* xp = reinterpret_cast<const float4*>(x) + (size_t)gw * (CHANNELS / 4);
    float4 a = __ldcs(xp + lane);
    float4 b = __ldcs(xp + 32 + lane);

    float f0 = a.x, f1 = a.y, f2 = a.z, f3 = a.w;
    float f4 = b.x, f5 = b.y, f6 = b.z, f7 = b.w;

    // Batcher odd-even mergesort for 8, descending (19 CE)
    ceF(f0,f1); ceF(f2,f3); ceF(f4,f5); ceF(f6,f7);
    ceF(f0,f2); ceF(f1,f3); ceF(f4,f6); ceF(f5,f7);
    ceF(f1,f2); ceF(f5,f6);
    ceF(f0,f4); ceF(f1,f5); ceF(f2,f6); ceF(f3,f7);
    ceF(f2,f4); ceF(f3,f5);
    ceF(f1,f2); ceF(f3,f4); ceF(f5,f6);
    // f0 >= f1 >= ... >= f7

    // per-lane count of {f_j >= c} via branchless binary search on sorted regs
    auto cnt8 = [&](float c) -> unsigned {
        bool c1 = (f3 >= c);
        float t1 = c1 ? f5 : f1;
        bool c2 = (t1 >= c);
        float tA = c2 ? f2 : f0;
        float tB = c2 ? f6 : f4;
        float t2 = c1 ? tB : tA;
        bool c3 = (t2 >= c);
        bool c0 = (f7 >= c);
        return 4u*(unsigned)c1 + 2u*(unsigned)c2 + (unsigned)c3 + (unsigned)c0;
    };

    unsigned cnt_pos = __reduce_add_sync(0xFFFFFFFFu, cnt8(0.0f));
    float thrf;

    if (cnt_pos >= KSEL) {
        // ---- HOT: T >= 0. Bisection on positive patterns. ----
        unsigned k0   = f2k(f0);                               // lane-max key
        unsigned keyL = __reduce_min_sync(0xFFFFFFFFu, k0);    // min lane-max
        unsigned keyM = __reduce_max_sync(0xFFFFFFFFu, k0);    // warp max (>=T>=0)
        // lower bound as positive pattern (clamp negatives to +0.0)
        unsigned lo = (keyL >= 0x80000000u) ? (keyL ^ 0x80000000u) : 0u;
        unsigned hi = (keyM ^ 0x80000000u) + 1u;               // cnt_ge(hi) == 0
        unsigned cntLo = 256u, cntHi = 0u;
        unsigned thrkey = lo;
        bool isolated = false;

        #pragma unroll 1
        while (hi - lo > 1u) {
            unsigned mid = (lo + hi) >> 1;
            unsigned tot = __reduce_add_sync(0xFFFFFFFFu, cnt8(__uint_as_float(mid)));
            if (tot >= KSEL) { lo = mid; cntLo = tot; }
            else             { hi = mid; cntHi = tot; }
            if (cntLo - cntHi == 1u) { isolated = true; break; }
        }
        if (isolated) {
            // exactly one element in [float(lo), float(hi)) -> it is T
            float Uf = __uint_as_float(hi);
            float pf = __uint_as_float(lo);
            float t = f7;
            t = (f6 < Uf) ? f6 : t;
            t = (f5 < Uf) ? f5 : t;
            t = (f4 < Uf) ? f4 : t;
            t = (f3 < Uf) ? f3 : t;
            t = (f2 < Uf) ? f2 : t;
            t = (f1 < Uf) ? f1 : t;
            t = (f0 < Uf) ? f0 : t;
            unsigned m = (t >= pf && t < Uf) ? __float_as_uint(t) : 0u;
            thrkey = __reduce_max_sync(0xFFFFFFFFu, m);
        } else {
            thrkey = lo;    // fully resolved: lo == bits(T)
        }
        thrf = __uint_as_float(thrkey);
    } else {
        // ---- COLD: T < 0. Exact key-domain radix (rarely taken). ----
        unsigned s0 = f2k(f0), s1 = f2k(f1), s2 = f2k(f2), s3 = f2k(f3);
        unsigned s4 = f2k(f4), s5 = f2k(f5), s6 = f2k(f6), s7 = f2k(f7);
        auto kcnt8 = [&](unsigned c) -> unsigned {
            bool c1 = (s3 >= c);
            unsigned t1 = c1 ? s5 : s1;
            bool c2 = (t1 >= c);
            unsigned tA = c2 ? s2 : s0;
            unsigned tB = c2 ? s6 : s4;
            unsigned t2 = c1 ? tB : tA;
            bool c3 = (t2 >= c);
            bool c0 = (s7 >= c);
            return 4u*(unsigned)c1 + 2u*(unsigned)c2 + (unsigned)c3 + (unsigned)c0;
        };
        unsigned prefix = 0u, U = 0xFFFFFFFFu;
        unsigned cntP = 256u, cntU = 0u;
        unsigned thrkey;
        #pragma unroll 1
        for (int bit = 31; ; --bit) {
            unsigned cand = prefix | (1u << bit);
            unsigned tot = __reduce_add_sync(0xFFFFFFFFu, kcnt8(cand));
            if (tot >= KSEL) { prefix = cand; cntP = tot; }
            else             { U = cand;      cntU = tot; }
            if (cntP - cntU == 1u) {
                unsigned t = s7;
                t = (s6 < U) ? s6 : t;
                t = (s5 < U) ? s5 : t;
                t = (s4 < U) ? s4 : t;
                t = (s3 < U) ? s3 : t;
                t = (s2 < U) ? s2 : t;
                t = (s1 < U) ? s1 : t;
                t = (s0 < U) ? s0 : t;
                unsigned m = (t >= prefix && t < U) ? t : 0u;
                thrkey = __reduce_max_sync(0xFFFFFFFFu, m);
                break;
            }
            if (bit == 0) { thrkey = prefix; break; }
        }
        unsigned tu = (thrkey & 0x80000000u) ? (thrkey ^ 0x80000000u) : ~thrkey;
        thrf = __uint_as_float(tu);
    }

    float4 oa, ob;
    oa.x = (a.x >= thrf) ? a.x : 0.0f;
    oa.y = (a.y >= thrf) ? a.y : 0.0f;
    oa.z = (a.z >= thrf) ? a.z : 0.0f;
    oa.w = (a.w >= thrf) ? a.w : 0.0f;
    ob.x = (b.x >= thrf) ? b.x : 0.0f;
    ob.y = (b.y >= thrf) ? b.y : 0.0f;
    ob.z = (b.z >= thrf) ? b.z : 0.0f;
    ob.w = (b.w >= thrf) ? b.w : 0.0f;

    float4* yp = reinterpret_cast<float4*>(y) + (size_t)gw * (CHANNELS / 4);
    __stcs(yp + lane, oa);
    __stcs(yp + 32 + lane, ob);
}

extern "C" void kernel_launch(void* const* d_in, const int* in_sizes, int n_in,
                              void* d_out, int out_size) {
    const float* x = (const float*)d_in[0];
    float* y = (float*)d_out;
    int rows = in_sizes[0] / CHANNELS;            // 200704
    int total_threads = rows * 32;                // one warp per row
    int block = 256;
    int grid = (total_threads + block - 1) / block;
    kwta_kernel<<<grid, block>>>(x, y, rows);
}